// round 1
// baseline (speedup 1.0000x reference)
#include <cuda_runtime.h>
#include <cstdint>

// Problem constants (fixed shapes for this problem instance)
#define T_DIM 64
#define U_DIM 142
#define I_DIM 4500
#define B_DIM 16384
#define K_TOP 10

// One warp per batch element.
// Lane owns users v = lane, lane+32, ..., lane+128 (5 slots; some invalid for v>=142).
__global__ __launch_bounds__(256) void ucf_kernel(
    const float* __restrict__ qos,       // [T, U, I]
    const float* __restrict__ user_avg,  // [T, U]
    const float* __restrict__ sim,       // [U, U]
    const int*   __restrict__ user_id,   // [B]
    const int*   __restrict__ item_id,   // [B]
    const int*   __restrict__ time_id,   // [B]
    float*       __restrict__ out)       // [B]
{
    const int warp = (blockIdx.x * blockDim.x + threadIdx.x) >> 5;
    const int lane = threadIdx.x & 31;
    if (warp >= B_DIM) return;

    const int t  = time_id[warp];
    const int u  = user_id[warp];
    const int it = item_id[warp];

    const float* qcol = qos + (size_t)t * (U_DIM * I_DIM) + it;  // + v*I
    const float* srow = sim + u * U_DIM;

    // --- Gather phase: 5 independent qos loads + 5 sim loads per lane ---
    float qv[5];
    float sv[5];
    unsigned long long key[5];

    #pragma unroll
    for (int j = 0; j < 5; j++) {
        const int v = lane + j * 32;
        float q = 0.f, s = 0.f;
        if (v < U_DIM) {
            q = __ldg(qcol + (size_t)v * I_DIM);   // scattered 32B sectors
            s = __ldg(srow + v);                   // coalesced
        }
        qv[j] = q;
        // sim_m = rated ? sim : 0.0
        const float sm = (v < U_DIM && q > 0.f) ? s : 0.f;
        sv[j] = sm;

        // Monotonic float->uint mapping: larger float => larger uint
        unsigned int bits = __float_as_uint(sm);
        bits = (bits & 0x80000000u) ? ~bits : (bits | 0x80000000u);
        // key: value desc, index asc on ties (jax.lax.top_k semantics)
        unsigned long long k64 =
            ((unsigned long long)bits << 32) | (unsigned long long)(0xFFFFFFFFu - (unsigned)v);
        if (v >= U_DIM) k64 = 0ull;   // below any valid key
        key[j] = k64;
    }

    // --- Top-K selection: 10 rounds of warp-argmax on 64-bit keys ---
    float S = 0.f;   // sum of selected sims
    float P = 0.f;   // sum of sim * (r_v - avg_v)

    #pragma unroll 1
    for (int r = 0; r < K_TOP; r++) {
        // local best among my 5 slots
        unsigned long long best = key[0];
        int bj = 0;
        #pragma unroll
        for (int j = 1; j < 5; j++) {
            if (key[j] > best) { best = key[j]; bj = j; }
        }
        // warp max (keys are unique per v, so exactly one winner lane)
        unsigned long long gbest = best;
        #pragma unroll
        for (int o = 16; o; o >>= 1) {
            unsigned long long other = __shfl_xor_sync(0xFFFFFFFFu, gbest, o);
            if (other > gbest) gbest = other;
        }
        if (best == gbest) {
            const int v = (int)(0xFFFFFFFFu - (unsigned)(gbest & 0xFFFFFFFFull));
            const float s  = sv[bj];
            const float rq = qv[bj];
            const float av = __ldg(user_avg + t * U_DIM + v);  // L1/L2 resident (36KB)
            S += s;
            P += s * (rq - av);
            key[bj] = 0ull;   // remove from candidate set
        }
    }

    // --- Warp reduce S, P ---
    #pragma unroll
    for (int o = 16; o; o >>= 1) {
        S += __shfl_xor_sync(0xFFFFFFFFu, S, o);
        P += __shfl_xor_sync(0xFFFFFFFFu, P, o);
    }

    if (lane == 0) {
        const float avg_u = __ldg(user_avg + t * U_DIM + u);
        out[warp] = avg_u + P / (S + 1e-8f);
    }
}

extern "C" void kernel_launch(void* const* d_in, const int* in_sizes, int n_in,
                              void* d_out, int out_size) {
    const float* qos      = (const float*)d_in[0];  // qos_tensor [T,U,I]
    const float* user_avg = (const float*)d_in[1];  // [T,U]
    const float* sim      = (const float*)d_in[2];  // user_sim_agg [U,U]
    const int*   user_id  = (const int*)d_in[3];    // [B]
    const int*   item_id  = (const int*)d_in[4];    // [B]
    const int*   time_id  = (const int*)d_in[5];    // [B]
    // d_in[6] = top_k (compile-time K_TOP=10)
    float* out = (float*)d_out;

    // 16384 warps, 8 warps per block -> 2048 blocks
    ucf_kernel<<<(B_DIM * 32) / 256, 256>>>(qos, user_avg, sim,
                                            user_id, item_id, time_id, out);
}

// round 2
// speedup vs baseline: 1.0887x; 1.0887x over previous
#include <cuda_runtime.h>
#include <cstdint>

#define T_DIM 64
#define U_DIM 142
#define I_DIM 4500
#define B_DIM 16384
#define K_TOP 10
#define MASK_WORDS 5   // ceil(142/32)

// Scratch: rated bitmask per (t, i): 64*4500*5 u32 = 5.76 MB
__device__ uint32_t g_mask[(size_t)T_DIM * I_DIM * MASK_WORDS];

// ---------------------------------------------------------------------------
// Phase A: streaming scan of qos -> packed rated bitmask.
// grid = (ceil(I/256), T), block = 256. Thread owns one item i; loops v.
// All loads coalesced (adjacent threads, adjacent i, same (t,v) row).
// ---------------------------------------------------------------------------
__global__ __launch_bounds__(256) void mask_kernel(const float* __restrict__ qos)
{
    const int t  = blockIdx.y;
    const int i0 = blockIdx.x * 256;
    const int i  = i0 + threadIdx.x;
    const bool active = (i < I_DIM);

    __shared__ uint32_t sm[256 * MASK_WORDS];

    const float* base = qos + (size_t)t * U_DIM * I_DIM + i;

    #pragma unroll
    for (int w = 0; w < MASK_WORDS; w++) {
        const int nb = (w < 4) ? 32 : (U_DIM - 128);   // word 4: 14 bits
        uint32_t m = 0;
        #pragma unroll
        for (int vb = 0; vb < 32; vb++) {
            if (vb < nb) {
                const int v = w * 32 + vb;
                const float q = active ? __ldg(base + (size_t)v * I_DIM) : 0.f;
                if (q > 0.f) m |= (1u << vb);
            }
        }
        sm[threadIdx.x * MASK_WORDS + w] = m;
    }
    __syncthreads();

    // Coalesced write of the 256*5-word tile (layout matches [i][w]).
    uint32_t* outp = g_mask + ((size_t)t * I_DIM + i0) * MASK_WORDS;
    const int nwords = (min(256, I_DIM - i0)) * MASK_WORDS;
    for (int k = (int)threadIdx.x; k < nwords; k += 256)
        outp[k] = sm[k];
}

// ---------------------------------------------------------------------------
// Phase B: per-batch-element top-K + prediction. One warp per element.
// Lane owns users v = lane + 32j (j<5). Rated bit for lane's user in word j
// is exactly bit `lane` of mask word j.
// ---------------------------------------------------------------------------
__global__ __launch_bounds__(256) void predict_kernel(
    const float* __restrict__ qos,
    const float* __restrict__ user_avg,
    const float* __restrict__ sim,
    const int*   __restrict__ user_id,
    const int*   __restrict__ item_id,
    const int*   __restrict__ time_id,
    float*       __restrict__ out)
{
    const int warp = (blockIdx.x * blockDim.x + threadIdx.x) >> 5;
    const int lane = threadIdx.x & 31;
    if (warp >= B_DIM) return;

    const int t  = time_id[warp];
    const int u  = user_id[warp];
    const int it = item_id[warp];

    const uint32_t* mrow = g_mask + ((size_t)t * I_DIM + it) * MASK_WORDS;
    const uint32_t  mw   = (lane < MASK_WORDS) ? mrow[lane] : 0u;

    const float* srow = sim + u * U_DIM;   // 80 KB matrix: L1/L2 resident

    // Build keys: rated -> sim, unrated(valid) -> 0.0 (matches jnp.where),
    // invalid lane-slot -> -inf sentinel.
    float key[5], sv[5];
    #pragma unroll
    for (int j = 0; j < 5; j++) {
        const int v = lane + 32 * j;
        const uint32_t m = __shfl_sync(0xFFFFFFFFu, mw, j);
        const bool valid = (v < U_DIM);
        const bool rated = valid && ((m >> lane) & 1u);
        const float s = valid ? __ldg(srow + v) : 0.f;
        const float k = rated ? s : (valid ? 0.f : -3.0e38f);
        key[j] = k;
        sv[j]  = k;
    }

    // 10 rounds of warp-argmax on 32-bit floats; ballot-elect one winner.
    // Value ties occur only at 0.0 (unrated), whose contribution is exactly 0,
    // so arbitrary election is exact w.r.t. the reference.
    unsigned sel = 0;
    #pragma unroll 1
    for (int r = 0; r < K_TOP; r++) {
        float best = key[0]; int bj = 0;
        #pragma unroll
        for (int j = 1; j < 5; j++)
            if (key[j] > best) { best = key[j]; bj = j; }

        float gb = best;
        #pragma unroll
        for (int o = 16; o; o >>= 1)
            gb = fmaxf(gb, __shfl_xor_sync(0xFFFFFFFFu, gb, o));

        const unsigned bal = __ballot_sync(0xFFFFFFFFu, best == gb);
        if (lane == (__ffs(bal) - 1)) {
            sel |= (1u << bj);
            key[bj] = -3.0e38f;   // remove from candidates
        }
    }

    // Gather qos / avg only for the <=10 selected users (high-MLP, predicated).
    float S = 0.f, P = 0.f;
    const float* qcol = qos + (size_t)t * U_DIM * I_DIM + it;
    const float* arow = user_avg + t * U_DIM;
    #pragma unroll
    for (int j = 0; j < 5; j++) {
        if (sel & (1u << j)) {
            const int v = lane + 32 * j;
            const float q  = __ldg(qcol + (size_t)v * I_DIM);
            const float av = __ldg(arow + v);
            const float s  = sv[j];
            S += s;
            P += s * (q - av);
        }
    }

    #pragma unroll
    for (int o = 16; o; o >>= 1) {
        S += __shfl_xor_sync(0xFFFFFFFFu, S, o);
        P += __shfl_xor_sync(0xFFFFFFFFu, P, o);
    }

    if (lane == 0) {
        const float avg_u = __ldg(arow + u);
        out[warp] = avg_u + P / (S + 1e-8f);
    }
}

// ---------------------------------------------------------------------------
extern "C" void kernel_launch(void* const* d_in, const int* in_sizes, int n_in,
                              void* d_out, int out_size) {
    const float* qos      = (const float*)d_in[0];  // [T,U,I]
    const float* user_avg = (const float*)d_in[1];  // [T,U]
    const float* sim      = (const float*)d_in[2];  // [U,U]
    const int*   user_id  = (const int*)d_in[3];    // [B]
    const int*   item_id  = (const int*)d_in[4];    // [B]
    const int*   time_id  = (const int*)d_in[5];    // [B]
    float* out = (float*)d_out;

    dim3 gridA((I_DIM + 255) / 256, T_DIM);         // 18 x 64 = 1152 CTAs
    mask_kernel<<<gridA, 256>>>(qos);

    predict_kernel<<<(B_DIM * 32) / 256, 256>>>(qos, user_avg, sim,
                                                user_id, item_id, time_id, out);
}